// round 15
// baseline (speedup 1.0000x reference)
#include <cuda_runtime.h>
#include <cuda_bf16.h>
#include <cstdint>

// Implicit-GEMM 3x3 conv via int8 tensor-core MMA (m16n8k32.s8), fp32 via
// fixed-point split:  x ~= QA*(256*ah+al),  w ~= QB*(256*bh+bl)  (int8 each)
//   out = QA*QB*( 65536*P1 + 256*P2 ),  P1 = ah*bh,  P2 = ah*bl + al*bh
// (al*bl dropped: ~3e-4 norm-relative). Integer accumulation is exact.

#define CONV_HW  56
#define CONV_PIX 3136
#define CONV_K   256
#define GEMM_K   2304
#define X_ELEMS  (32 * 256 * CONV_PIX)
#define W_ELEMS  (CONV_K * GEMM_K)
#define BK       64
#define NCHUNK   (GEMM_K / BK)             // 36

#define QA (8.0f / 32768.0f)
#define QB (0.4f / 32768.0f)
#define INV_QA 4096.0f                     // 32768/8
#define INV_QB 81920.0f                    // 32768/0.4

#define PITCH_B  80                        // bytes per smem row (64 payload + 16 pad)
#define A_BYTES  (128 * PITCH_B)           // 10240
#define B_BYTES  (128 * PITCH_B)           // 10240
#define OFF_AL   A_BYTES
#define OFF_BH   (2 * A_BYTES)
#define OFF_BL   (2 * A_BYTES + B_BYTES)
#define STAGE    (2 * A_BYTES + 2 * B_BYTES)   // 40960
#define SMEM_TOTAL (2 * STAGE)             // 81920

__device__ unsigned short g_xs[X_ELEMS];   // byte0 = ah, byte1 = al
__device__ signed char    g_wbh[W_ELEMS];
__device__ signed char    g_wbl[W_ELEMS];

__device__ __forceinline__ uint32_t smem_u32(const void* p) {
    uint32_t a;
    asm("{ .reg .u64 t; cvta.to.shared.u64 t, %1; cvt.u32.u64 %0, t; }" : "=r"(a) : "l"(p));
    return a;
}
__device__ __forceinline__ uint32_t prmt(uint32_t a, uint32_t b, uint32_t sel) {
    uint32_t r;
    asm("prmt.b32 %0, %1, %2, %3;" : "=r"(r) : "r"(a), "r"(b), "r"(sel));
    return r;
}
__device__ __forceinline__ void cp_async16(uint32_t dst, const void* src) {
    asm volatile("cp.async.ca.shared.global [%0], [%1], 16;" :: "r"(dst), "l"(src));
}
#define CP_COMMIT() asm volatile("cp.async.commit_group;" ::: "memory")
#define CP_WAIT0()  asm volatile("cp.async.wait_group 0;" ::: "memory")

#define LDSM_X4(r0, r1, r2, r3, a) \
    asm volatile("ldmatrix.sync.aligned.m8n8.x4.shared.b16 {%0,%1,%2,%3}, [%4];" \
                 : "=r"(r0), "=r"(r1), "=r"(r2), "=r"(r3) : "r"(a))

#define IMMA16832(c, a, b) \
    asm volatile("mma.sync.aligned.m16n8k32.row.col.s32.s8.s8.s32 " \
                 "{%0,%1,%2,%3}, {%4,%5,%6,%7}, {%8,%9}, {%0,%1,%2,%3};" \
                 : "+r"((c)[0]), "+r"((c)[1]), "+r"((c)[2]), "+r"((c)[3]) \
                 : "r"((a)[0]), "r"((a)[1]), "r"((a)[2]), "r"((a)[3]), \
                   "r"((b)[0]), "r"((b)[1]))

// ---------------- prep kernels ----------------

__device__ __forceinline__ unsigned short quant_pair(float v, float inv) {
    float t = fminf(fmaxf(v * inv, -32639.f), 32639.f);
    float ahf = rintf(t * 0.00390625f);               // /256
    ahf = fminf(fmaxf(ahf, -127.f), 127.f);
    int ah = (int)ahf;
    int al = (int)rintf(t - 256.f * ahf);
    al = al > 127 ? 127 : (al < -127 ? -127 : al);
    return (unsigned short)((ah & 0xFF) | ((al & 0xFF) << 8));
}

__global__ void quant_x_kernel(const float* __restrict__ x) {
    const int i4 = blockIdx.x * blockDim.x + threadIdx.x;
    if (i4 * 4 >= X_ELEMS) return;
    const float4 v = *(const float4*)(x + (size_t)i4 * 4);
    ushort4 o;
    o.x = quant_pair(v.x, INV_QA);
    o.y = quant_pair(v.y, INV_QA);
    o.z = quant_pair(v.z, INV_QA);
    o.w = quant_pair(v.w, INV_QA);
    *(ushort4*)(g_xs + (size_t)i4 * 4) = o;
}

__global__ void quant_w_kernel(const float* __restrict__ w) {
    const int i = blockIdx.x * blockDim.x + threadIdx.x;
    if (i >= W_ELEMS) return;
    unsigned short p = quant_pair(w[i], INV_QB);
    g_wbh[i] = (signed char)(p & 0xFF);
    g_wbl[i] = (signed char)((p >> 8) & 0xFF);
}

// ---------------- main kernel ----------------

__global__ __launch_bounds__(512, 1)
void conv3x3_imma_kernel(float* __restrict__ out) {
    extern __shared__ char smem[];
    const uint32_t sbase = smem_u32(smem);
    const int tid  = threadIdx.x;
    const int wrp  = tid >> 5;
    const int lane = tid & 31;

    const int block_m = blockIdx.x * 128;
    const int block_n = blockIdx.y * 128;

    // ---- A staging: m = tid&127, kg = (tid>>7)*16 (16 k's each)
    const int a_m  = tid & 127;
    const int a_kg = (tid >> 7) * 16;
    const int p_a    = block_m + a_m;
    const int nimg_a = p_a / CONV_PIX;
    const int hw_a   = p_a - nimg_a * CONV_PIX;
    const int oh     = hw_a / CONV_HW;
    const int ow     = hw_a - oh * CONV_HW;
    const unsigned short* xs_n = g_xs + (size_t)nimg_a * CONV_K * CONV_PIX;

    // ---- B staging via cp.async: row = tid>>2 (0..127), off = (tid&3)*16
    const int b_row = tid >> 2;
    const int b_off = (tid & 3) * 16;
    const signed char* wbh = g_wbh + (size_t)(block_n + b_row) * GEMM_K + b_off;
    const signed char* wbl = g_wbl + (size_t)(block_n + b_row) * GEMM_K + b_off;
    const uint32_t b_sts = (uint32_t)b_row * PITCH_B + (uint32_t)b_off;

    // ---- warp tile 32x32: warp_m = wrp&3, warp_n = wrp>>2
    const int m0 = (wrp & 3) * 32;
    const int n0 = (wrp >> 2) * 32;

    const uint32_t a_lm_off = (uint32_t)(m0 + (lane & 15)) * PITCH_B + (uint32_t)(lane >> 4) * 16;
    const uint32_t b_lm_off = (uint32_t)(n0 + (lane & 7) + ((lane >> 4) << 3)) * PITCH_B
                            + (uint32_t)((lane >> 3) & 1) * 16;

    int accA[2][4][4], accB[2][4][4];
    #pragma unroll
    for (int i = 0; i < 2; i++)
        #pragma unroll
        for (int j = 0; j < 4; j++)
            #pragma unroll
            for (int r = 0; r < 4; r++) { accA[i][j][r] = 0; accB[i][j][r] = 0; }

    unsigned short axv[16];

    auto load_A = [&](int kt) {
        int k0 = kt + a_kg;
        int c  = k0 / 9;
        int rs = k0 - c * 9;
        int r  = rs / 3;
        int s  = rs - r * 3;
        const unsigned short* xc = xs_n + c * CONV_PIX;
        #pragma unroll
        for (int j = 0; j < 16; j++) {
            const int ih = oh + r - 1, iw = ow + s - 1;
            const bool ok = ((unsigned)ih < CONV_HW) && ((unsigned)iw < CONV_HW);
            axv[j] = ok ? __ldg(xc + ih * CONV_HW + iw) : (unsigned short)0;
            if (++s == 3) { s = 0; if (++r == 3) { r = 0; xc += CONV_PIX; } }
        }
    };
    auto store_A = [&](char* st) {
        uint32_t hi[4], lo[4];
        #pragma unroll
        for (int t = 0; t < 4; t++) {
            const uint32_t p01 = (uint32_t)axv[4*t+0] | ((uint32_t)axv[4*t+1] << 16);
            const uint32_t p23 = (uint32_t)axv[4*t+2] | ((uint32_t)axv[4*t+3] << 16);
            hi[t] = prmt(p01, p23, 0x6420);
            lo[t] = prmt(p01, p23, 0x7531);
        }
        const uint32_t off = (uint32_t)a_m * PITCH_B + (uint32_t)a_kg;
        *(uint4*)(st + off)          = make_uint4(hi[0], hi[1], hi[2], hi[3]);
        *(uint4*)(st + OFF_AL + off) = make_uint4(lo[0], lo[1], lo[2], lo[3]);
    };
    auto issue_B = [&](uint32_t sstage, int kt) {
        cp_async16(sstage + OFF_BH + b_sts, wbh + kt);
        cp_async16(sstage + OFF_BL + b_sts, wbl + kt);
        CP_COMMIT();
    };

    auto ldA2 = [&](uint32_t sstage, uint32_t base, uint32_t kso, uint32_t (&a)[2][4]) {
        #pragma unroll
        for (int mt = 0; mt < 2; mt++)
            LDSM_X4(a[mt][0], a[mt][1], a[mt][2], a[mt][3],
                    sstage + base + a_lm_off + kso + (uint32_t)mt * 16 * PITCH_B);
    };
    auto ldB2 = [&](uint32_t sstage, uint32_t base, uint32_t kso, uint32_t (&b)[2][4]) {
        LDSM_X4(b[0][0], b[0][1], b[0][2], b[0][3], sstage + base + b_lm_off + kso);
        LDSM_X4(b[1][0], b[1][1], b[1][2], b[1][3], sstage + base + b_lm_off + kso + 16 * PITCH_B);
    };
    auto mma_pass = [&](uint32_t (&a)[2][4], uint32_t (&b)[2][4], int (&acc)[2][4][4]) {
        #pragma unroll
        for (int mt = 0; mt < 2; mt++)
            #pragma unroll
            for (int nt = 0; nt < 4; nt++)
                IMMA16832(acc[mt][nt], a[mt], &b[nt >> 1][(nt & 1) * 2]);
    };

    // prologue: stage chunk 0 into buffer 0
    issue_B(sbase, 0);
    load_A(0);
    store_A(smem);
    CP_WAIT0();
    __syncthreads();

    for (int c = 0; c < NCHUNK; ++c) {
        const int buf = c & 1;
        const uint32_t sstage = sbase + (uint32_t)buf * STAGE;
        const bool more = (c + 1) < NCHUNK;

        if (more) {
            issue_B(sbase + (uint32_t)(buf ^ 1) * STAGE, (c + 1) * BK);
            load_A((c + 1) * BK);
        }

        #pragma unroll
        for (int ks = 0; ks < 2; ks++) {
            const uint32_t kso = (uint32_t)ks * 32;
            uint32_t a_h[2][4], a_l[2][4], b[2][4];

            ldB2(sstage, OFF_BH, kso, b);       // Bh
            ldA2(sstage, 0,      kso, a_h);
            mma_pass(a_h, b, accA);             // P1: Ah*Bh
            ldA2(sstage, OFF_AL, kso, a_l);
            mma_pass(a_l, b, accB);             // P3: Al*Bh   (b dies)
            ldB2(sstage, OFF_BL, kso, b);       // Bl overwrites
            if (ks == 0 && more) store_A(smem + (buf ^ 1) * STAGE);  // axv dies
            mma_pass(a_h, b, accB);             // P2: Ah*Bl
        }

        CP_WAIT0();
        __syncthreads();
    }

    // ---- epilogue: out = QA*QB*(65536*P1 + 256*P2)
    const float s = QA * QB;
    const int oc_base = block_n + n0 + (lane & 3) * 2;
    #pragma unroll
    for (int mt = 0; mt < 2; mt++) {
        const int p_lo = block_m + m0 + mt * 16 + (lane >> 2);
        const int p_hi = p_lo + 8;
        const int nl = p_lo / CONV_PIX, hl = p_lo - nl * CONV_PIX;
        const int nh = p_hi / CONV_PIX, hh = p_hi - nh * CONV_PIX;
        float* olo = out + (size_t)nl * CONV_K * CONV_PIX + hl;
        float* ohi = out + (size_t)nh * CONV_K * CONV_PIX + hh;
        #pragma unroll
        for (int nt = 0; nt < 4; nt++) {
            const int oc = oc_base + nt * 8;
            float v0 = s * (65536.f * (float)accA[mt][nt][0] + 256.f * (float)accB[mt][nt][0]);
            float v1 = s * (65536.f * (float)accA[mt][nt][1] + 256.f * (float)accB[mt][nt][1]);
            float v2 = s * (65536.f * (float)accA[mt][nt][2] + 256.f * (float)accB[mt][nt][2]);
            float v3 = s * (65536.f * (float)accA[mt][nt][3] + 256.f * (float)accB[mt][nt][3]);
            olo[(size_t)(oc    ) * CONV_PIX] = v0;
            olo[(size_t)(oc + 1) * CONV_PIX] = v1;
            ohi[(size_t)(oc    ) * CONV_PIX] = v2;
            ohi[(size_t)(oc + 1) * CONV_PIX] = v3;
        }
    }
}

extern "C" void kernel_launch(void* const* d_in, const int* in_sizes, int n_in,
                              void* d_out, int out_size) {
    const float* x = (const float*)d_in[0];
    const float* w = (const float*)d_in[1];
    float* out = (float*)d_out;

    quant_x_kernel<<<(X_ELEMS / 4 + 255) / 256, 256>>>(x);
    quant_w_kernel<<<(W_ELEMS + 255) / 256, 256>>>(w);

    cudaFuncSetAttribute(conv3x3_imma_kernel,
                         cudaFuncAttributeMaxDynamicSharedMemorySize, SMEM_TOTAL);
    dim3 grid(784, 2);
    conv3x3_imma_kernel<<<grid, 512, SMEM_TOTAL>>>(out);
}

// round 16
// speedup vs baseline: 4.6733x; 4.6733x over previous
#include <cuda_runtime.h>
#include <cuda_fp16.h>
#include <cstdint>

// Implicit-GEMM 3x3 conv, SINGLE-PASS fp16 tensor-core MMA with fp32 accum.
// Error model (validated by R12's int8 run): per-operand fp16 rounding 2^-12
// -> norm rel_err ~3.4e-4 < 1e-3 threshold.
// GEMM: Out[p][oc] = sum_k A[p][k] * W2d[oc][k];  M=100352, N=256, K=2304.

#define CONV_HW  56
#define CONV_PIX 3136
#define CONV_K   256
#define GEMM_K   2304
#define X_ELEMS  (32 * 256 * CONV_PIX)
#define W_ELEMS  (CONV_K * GEMM_K)
#define BK       64
#define NCHUNK   (GEMM_K / BK)             // 36

#define PITCH_B  144                       // 64 fp16 payload (128B) + 16B pad
#define A_BYTES  (128 * PITCH_B)           // 18432
#define B_BYTES  (256 * PITCH_B)           // 36864
#define OFF_B    A_BYTES
#define STAGE    (A_BYTES + B_BYTES)       // 55296
#define SMEM_TOTAL (2 * STAGE)             // 110592

__device__ unsigned short g_xh[X_ELEMS];   // fp16 bits of x
__device__ unsigned short g_wh[W_ELEMS];   // fp16 bits of w

__device__ __forceinline__ uint32_t smem_u32(const void* p) {
    uint32_t a;
    asm("{ .reg .u64 t; cvta.to.shared.u64 t, %1; cvt.u32.u64 %0, t; }" : "=r"(a) : "l"(p));
    return a;
}
__device__ __forceinline__ void cp_async16(uint32_t dst, const void* src) {
    asm volatile("cp.async.ca.shared.global [%0], [%1], 16;" :: "r"(dst), "l"(src));
}
#define CP_COMMIT() asm volatile("cp.async.commit_group;" ::: "memory")
#define CP_WAIT0()  asm volatile("cp.async.wait_group 0;" ::: "memory")

#define LDSM_X4(r0, r1, r2, r3, a) \
    asm volatile("ldmatrix.sync.aligned.m8n8.x4.shared.b16 {%0,%1,%2,%3}, [%4];" \
                 : "=r"(r0), "=r"(r1), "=r"(r2), "=r"(r3) : "r"(a))

#define MMAF16(c, a, b) \
    asm volatile("mma.sync.aligned.m16n8k16.row.col.f32.f16.f16.f32 " \
                 "{%0,%1,%2,%3}, {%4,%5,%6,%7}, {%8,%9}, {%0,%1,%2,%3};" \
                 : "+f"((c)[0]), "+f"((c)[1]), "+f"((c)[2]), "+f"((c)[3]) \
                 : "r"((a)[0]), "r"((a)[1]), "r"((a)[2]), "r"((a)[3]), \
                   "r"((b)[0]), "r"((b)[1]))

// ---------------- prep kernels ----------------

__global__ void cvt_x_kernel(const float* __restrict__ x) {
    const int i8 = blockIdx.x * blockDim.x + threadIdx.x;
    if (i8 * 8 >= X_ELEMS) return;
    const float4 v0 = *(const float4*)(x + (size_t)i8 * 8);
    const float4 v1 = *(const float4*)(x + (size_t)i8 * 8 + 4);
    __half2 h0 = __floats2half2_rn(v0.x, v0.y);
    __half2 h1 = __floats2half2_rn(v0.z, v0.w);
    __half2 h2 = __floats2half2_rn(v1.x, v1.y);
    __half2 h3 = __floats2half2_rn(v1.z, v1.w);
    uint4 o;
    o.x = *reinterpret_cast<uint32_t*>(&h0);
    o.y = *reinterpret_cast<uint32_t*>(&h1);
    o.z = *reinterpret_cast<uint32_t*>(&h2);
    o.w = *reinterpret_cast<uint32_t*>(&h3);
    *(uint4*)(g_xh + (size_t)i8 * 8) = o;
}

__global__ void cvt_w_kernel(const float* __restrict__ w) {
    const int i = blockIdx.x * blockDim.x + threadIdx.x;
    if (i * 2 >= W_ELEMS) return;
    const float2 v = *(const float2*)(w + (size_t)i * 2);
    __half2 h = __floats2half2_rn(v.x, v.y);
    *(uint32_t*)(g_wh + (size_t)i * 2) = *reinterpret_cast<uint32_t*>(&h);
}

// ---------------- main kernel ----------------

__global__ __launch_bounds__(512, 1)
void conv3x3_f16_kernel(float* __restrict__ out) {
    extern __shared__ char smem[];
    const uint32_t sbase = smem_u32(smem);
    const int tid  = threadIdx.x;
    const int wrp  = tid >> 5;
    const int lane = tid & 31;

    const int block_m = blockIdx.x * 128;   // grid.y == 1: CTA covers all 256 oc

    // ---- A staging: m = tid&127, kg = (tid>>7)*16  (16 fp16 per thread)
    const int a_m  = tid & 127;
    const int a_kg = (tid >> 7) * 16;
    const int p_a    = block_m + a_m;
    const int nimg_a = p_a / CONV_PIX;
    const int hw_a   = p_a - nimg_a * CONV_PIX;
    const int oh     = hw_a / CONV_HW;
    const int ow     = hw_a - oh * CONV_HW;
    const unsigned short* xs_n = g_xh + (size_t)nimg_a * CONV_K * CONV_PIX;

    // ---- B staging via cp.async: row = tid>>1 (0..255), 4x16B per thread
    const int b_row = tid >> 1;
    const int b_q0  = (tid & 1) * 4;       // quad offset 0 or 4 (of 8)
    const unsigned short* whp = g_wh + (size_t)b_row * GEMM_K + b_q0 * 8;
    const uint32_t b_sts = (uint32_t)b_row * PITCH_B + (uint32_t)b_q0 * 16;

    // ---- warp tile 32x64: warp_m = wrp&3, warp_n = wrp>>2
    const int m0 = (wrp & 3) * 32;
    const int n0 = (wrp >> 2) * 64;

    const uint32_t a_lm_off = (uint32_t)(m0 + (lane & 15)) * PITCH_B + (uint32_t)(lane >> 4) * 16;
    const uint32_t b_lm_off = (uint32_t)(n0 + (lane & 7) + ((lane >> 4) << 3)) * PITCH_B
                            + (uint32_t)((lane >> 3) & 1) * 16;

    float acc[2][8][4];
    #pragma unroll
    for (int i = 0; i < 2; i++)
        #pragma unroll
        for (int j = 0; j < 8; j++)
            #pragma unroll
            for (int r = 0; r < 4; r++) acc[i][j][r] = 0.f;

    unsigned short axv[16];

    auto load_A = [&](int kt) {
        int k0 = kt + a_kg;
        int c  = k0 / 9;
        int rs = k0 - c * 9;
        int r  = rs / 3;
        int s  = rs - r * 3;
        const unsigned short* xc = xs_n + c * CONV_PIX;
        #pragma unroll
        for (int j = 0; j < 16; j++) {
            const int ih = oh + r - 1, iw = ow + s - 1;
            const bool ok = ((unsigned)ih < CONV_HW) && ((unsigned)iw < CONV_HW);
            axv[j] = ok ? __ldg(xc + ih * CONV_HW + iw) : (unsigned short)0;
            if (++s == 3) { s = 0; if (++r == 3) { r = 0; xc += CONV_PIX; } }
        }
    };
    auto store_A = [&](char* st) {
        uint32_t p[8];
        #pragma unroll
        for (int t = 0; t < 8; t++)
            p[t] = (uint32_t)axv[2*t] | ((uint32_t)axv[2*t+1] << 16);
        const uint32_t off = (uint32_t)a_m * PITCH_B + (uint32_t)a_kg * 2;
        *(uint4*)(st + off)      = make_uint4(p[0], p[1], p[2], p[3]);
        *(uint4*)(st + off + 16) = make_uint4(p[4], p[5], p[6], p[7]);
    };
    auto issue_B = [&](uint32_t sstage, int kt) {
        #pragma unroll
        for (int q = 0; q < 4; q++)
            cp_async16(sstage + OFF_B + b_sts + q * 16, whp + kt + q * 8);
        CP_COMMIT();
    };

    auto ldA2 = [&](uint32_t sstage, uint32_t kso, uint32_t (&a)[2][4]) {
        #pragma unroll
        for (int mt = 0; mt < 2; mt++)
            LDSM_X4(a[mt][0], a[mt][1], a[mt][2], a[mt][3],
                    sstage + a_lm_off + kso + (uint32_t)mt * 16 * PITCH_B);
    };
    auto ldB4 = [&](uint32_t sstage, uint32_t kso, uint32_t (&b)[4][4]) {
        #pragma unroll
        for (int t = 0; t < 4; t++)
            LDSM_X4(b[t][0], b[t][1], b[t][2], b[t][3],
                    sstage + OFF_B + b_lm_off + kso + (uint32_t)t * 16 * PITCH_B);
    };
    auto mma_pass = [&](uint32_t (&a)[2][4], uint32_t (&b)[4][4]) {
        #pragma unroll
        for (int mt = 0; mt < 2; mt++)
            #pragma unroll
            for (int nt = 0; nt < 8; nt++)
                MMAF16(acc[mt][nt], a[mt], &b[nt >> 1][(nt & 1) * 2]);
    };

    // prologue
    issue_B(sbase, 0);
    load_A(0);
    store_A(smem);
    CP_WAIT0();
    __syncthreads();

    for (int c = 0; c < NCHUNK; ++c) {
        const int buf = c & 1;
        const uint32_t sstage = sbase + (uint32_t)buf * STAGE;
        const bool more = (c + 1) < NCHUNK;

        if (more) {
            issue_B(sbase + (uint32_t)(buf ^ 1) * STAGE, (c + 1) * BK);
            load_A((c + 1) * BK);
        }

        #pragma unroll
        for (int ks = 0; ks < 4; ks++) {      // 4 x k16 per BK=64 chunk
            const uint32_t kso = (uint32_t)ks * 32;
            uint32_t a[2][4], b[4][4];
            ldB4(sstage, kso, b);
            ldA2(sstage, kso, a);
            if (ks == 0 && more) store_A(smem + (buf ^ 1) * STAGE);  // axv dies
            mma_pass(a, b);
        }

        CP_WAIT0();
        __syncthreads();
    }

    // ---- epilogue: 64 floats per thread
    const int oc_base = n0 + (lane & 3) * 2;
    #pragma unroll
    for (int mt = 0; mt < 2; mt++) {
        const int p_lo = block_m + m0 + mt * 16 + (lane >> 2);
        const int p_hi = p_lo + 8;
        const int nl = p_lo / CONV_PIX, hl = p_lo - nl * CONV_PIX;
        const int nh = p_hi / CONV_PIX, hh = p_hi - nh * CONV_PIX;
        float* olo = out + (size_t)nl * CONV_K * CONV_PIX + hl;
        float* ohi = out + (size_t)nh * CONV_K * CONV_PIX + hh;
        #pragma unroll
        for (int nt = 0; nt < 8; nt++) {
            const int oc = oc_base + nt * 8;
            olo[(size_t)(oc    ) * CONV_PIX] = acc[mt][nt][0];
            olo[(size_t)(oc + 1) * CONV_PIX] = acc[mt][nt][1];
            ohi[(size_t)(oc    ) * CONV_PIX] = acc[mt][nt][2];
            ohi[(size_t)(oc + 1) * CONV_PIX] = acc[mt][nt][3];
        }
    }
}

extern "C" void kernel_launch(void* const* d_in, const int* in_sizes, int n_in,
                              void* d_out, int out_size) {
    const float* x = (const float*)d_in[0];
    const float* w = (const float*)d_in[1];
    float* out = (float*)d_out;

    cvt_x_kernel<<<(X_ELEMS / 8 + 255) / 256, 256>>>(x);
    cvt_w_kernel<<<(W_ELEMS / 2 + 255) / 256, 256>>>(w);

    cudaFuncSetAttribute(conv3x3_f16_kernel,
                         cudaFuncAttributeMaxDynamicSharedMemorySize, SMEM_TOTAL);
    dim3 grid(784, 1);   // 128-pixel M tiles; CTA covers all 256 oc
    conv3x3_f16_kernel<<<grid, 512, SMEM_TOTAL>>>(out);
}